// round 4
// baseline (speedup 1.0000x reference)
#include <cuda_runtime.h>
#include <cuda_bf16.h>
#include <math.h>

#define NN 50000
#define EE 800000
#define DIN 500
#define HH 256
#define CC 7

#define KPAD 512
#define MPAD 50048           // 391 * 128
#define MTILES 391

__device__ float g_x0[NN * HH];
__device__ float g_xa[NN * HH];
__device__ float g_xb[NN * HH];
__device__ float g_al[2][NN];
__device__ float g_ar[2][NN];

__device__ __nv_bfloat16 g_Ahi[(size_t)MPAD * KPAD];
__device__ __nv_bfloat16 g_Alo[(size_t)MPAD * KPAD];
__device__ __nv_bfloat16 g_Bhi[HH * KPAD];
__device__ __nv_bfloat16 g_Blo[HH * KPAD];

__device__ int g_deg[NN];
__device__ int g_tmp[NN];
__device__ int g_bsum[64];
__device__ int g_rowptr[NN + 1];
__device__ int g_cursor[NN];
__device__ int g_csr_src[EE];
__device__ float g_gate[EE];

__device__ __forceinline__ float warp_sum(float v) {
#pragma unroll
    for (int o = 16; o; o >>= 1) v += __shfl_xor_sync(0xffffffffu, v, o);
    return v;
}

__device__ __forceinline__ float dot4(float4 a, float4 b) {
    return a.x * b.x + a.y * b.y + a.z * b.z + a.w * b.w;
}

// ================= split kernels: fp32 -> bf16 hi/lo =================
__device__ __forceinline__ void split_store(__nv_bfloat16* hi, __nv_bfloat16* lo,
                                            size_t off, float4 v) {
    float vv[4] = {v.x, v.y, v.z, v.w};
    __nv_bfloat16 h[4], l[4];
#pragma unroll
    for (int i = 0; i < 4; i++) {
        h[i] = __float2bfloat16(vv[i]);
        l[i] = __float2bfloat16(vv[i] - __bfloat162float(h[i]));
    }
    *(uint2*)(hi + off) = *(uint2*)h;
    *(uint2*)(lo + off) = *(uint2*)l;
}

__global__ void k_splitA(const float* __restrict__ x) {
    int idx = blockIdx.x * blockDim.x + threadIdx.x;
    if (idx >= MPAD * (KPAD / 4)) return;
    int row = idx >> 7, ch = idx & 127;
    int rsrc = row < NN ? row : NN - 1;
    float4 v = make_float4(0.f, 0.f, 0.f, 0.f);
    if (ch < DIN / 4)
        v = *(const float4*)(x + (size_t)rsrc * DIN + ch * 4);
    split_store(g_Ahi, g_Alo, (size_t)row * KPAD + ch * 4, v);
}

__global__ void k_splitB(const float* __restrict__ W) {
    int idx = blockIdx.x * blockDim.x + threadIdx.x;
    if (idx >= HH * (KPAD / 4)) return;
    int row = idx >> 7, ch = idx & 127;
    float4 v = make_float4(0.f, 0.f, 0.f, 0.f);
    if (ch < DIN / 4)
        v = *(const float4*)(W + (size_t)row * DIN + ch * 4);
    split_store(g_Bhi, g_Blo, (size_t)row * KPAD + ch * 4, v);
}

// ================= tensor-core GEMM (split-bf16, 3 products) =================
// out[m][n] = sum_k A[m][k]*B[n][k] + bias[n]   (= x @ W^T + b)
// CTA tile 128x128, 8 warps of 64x32, K-tile 32, double-buffered cp.async.
// smem per array tile: 128 rows x 5 chunks x 16B = 10240 B  (stride-5 padding)
#define TILE_B 10240
#define STAGE_B (4 * TILE_B)

__device__ __forceinline__ void cp16(unsigned s, const void* g) {
    asm volatile("cp.async.cg.shared.global [%0], [%1], 16;" :: "r"(s), "l"(g));
}
__device__ __forceinline__ void ldm4(unsigned* r, unsigned addr) {
    asm volatile("ldmatrix.sync.aligned.m8n8.x4.shared.b16 {%0,%1,%2,%3}, [%4];"
                 : "=r"(r[0]), "=r"(r[1]), "=r"(r[2]), "=r"(r[3]) : "r"(addr));
}
__device__ __forceinline__ void mma16816(float* c, const unsigned* a, const unsigned* b) {
    asm volatile(
        "mma.sync.aligned.m16n8k16.row.col.f32.bf16.bf16.f32 "
        "{%0,%1,%2,%3}, {%4,%5,%6,%7}, {%8,%9}, {%0,%1,%2,%3};"
        : "+f"(c[0]), "+f"(c[1]), "+f"(c[2]), "+f"(c[3])
        : "r"(a[0]), "r"(a[1]), "r"(a[2]), "r"(a[3]), "r"(b[0]), "r"(b[1]));
}

__global__ __launch_bounds__(256, 1) void k_gemm_tc(const float* __restrict__ bias) {
    extern __shared__ char smem[];
    unsigned sbase = (unsigned)__cvta_generic_to_shared(smem);
    int tid = threadIdx.x;
    int lane = tid & 31;
    int wid = tid >> 5;
    int warp_m = wid & 1;   // 2 in M
    int warp_n = wid >> 1;  // 4 in N
    size_t m0 = (size_t)blockIdx.x * 128;
    size_t n0 = (size_t)blockIdx.y * 128;

    float acc[4][4][4] = {};

    // copy one K-tile (kt) into stage st
    auto copy_tile = [&](int kt, int st) {
        unsigned sb = sbase + st * STAGE_B;
#pragma unroll
        for (int i = 0; i < 8; i++) {
            int cid = ((i & 1) << 8) + tid;      // 0..511 within array
            int row = cid >> 2, ch = cid & 3;
            size_t goff = (size_t)row * KPAD + kt * 32 + ch * 8;
            const __nv_bfloat16* gp;
            unsigned so;
            if (i < 2)      { gp = g_Ahi + m0 * KPAD + goff; so = 0; }
            else if (i < 4) { gp = g_Alo + m0 * KPAD + goff; so = TILE_B; }
            else if (i < 6) { gp = g_Bhi + n0 * KPAD + goff; so = 2 * TILE_B; }
            else            { gp = g_Blo + n0 * KPAD + goff; so = 3 * TILE_B; }
            cp16(sb + so + (row * 5 + ch) * 16, gp);
        }
    };

    // ldmatrix per-lane row/chunk selectors
    int a_row = (lane & 7) + ((lane >> 3) & 1) * 8;
    int a_chk = (lane >> 4) & 1;
    int b_row = (lane & 7) + ((lane >> 4) & 1) * 8;
    int b_chk = (lane >> 3) & 1;

    copy_tile(0, 0);
    asm volatile("cp.async.commit_group;");

    const int NKT = KPAD / 32;  // 16
    for (int kt = 0; kt < NKT; kt++) {
        int cur = kt & 1;
        if (kt + 1 < NKT) copy_tile(kt + 1, 1 - cur);
        asm volatile("cp.async.commit_group;");
        asm volatile("cp.async.wait_group 1;");
        __syncthreads();

        unsigned sb = sbase + cur * STAGE_B;
#pragma unroll
        for (int k16 = 0; k16 < 2; k16++) {
            unsigned Ah[4][4], Al[4][4], Bh[2][4], Bl[2][4];
#pragma unroll
            for (int mf = 0; mf < 4; mf++) {
                int row = warp_m * 64 + mf * 16 + a_row;
                unsigned off = (row * 5 + k16 * 2 + a_chk) * 16;
                ldm4(Ah[mf], sb + off);
                ldm4(Al[mf], sb + TILE_B + off);
            }
#pragma unroll
            for (int np = 0; np < 2; np++) {
                int row = warp_n * 32 + np * 16 + b_row;
                unsigned off = (row * 5 + k16 * 2 + b_chk) * 16;
                ldm4(Bh[np], sb + 2 * TILE_B + off);
                ldm4(Bl[np], sb + 3 * TILE_B + off);
            }
#pragma unroll
            for (int mf = 0; mf < 4; mf++)
#pragma unroll
                for (int nf = 0; nf < 4; nf++) {
                    const unsigned* bh = &Bh[nf >> 1][(nf & 1) * 2];
                    const unsigned* bl = &Bl[nf >> 1][(nf & 1) * 2];
                    mma16816(acc[mf][nf], Ah[mf], bh);
                    mma16816(acc[mf][nf], Ah[mf], bl);
                    mma16816(acc[mf][nf], Al[mf], bh);
                }
        }
        __syncthreads();
    }

    // epilogue
    int r0 = lane >> 2, c0 = (lane & 3) * 2;
#pragma unroll
    for (int nf = 0; nf < 4; nf++) {
        int n = (int)n0 + warp_n * 32 + nf * 8 + c0;
        float b0 = bias[n], b1 = bias[n + 1];
#pragma unroll
        for (int mf = 0; mf < 4; mf++) {
            int m = (int)m0 + warp_m * 64 + mf * 16 + r0;
            float* o = g_x0 + (size_t)m * HH + n;
            if (m < NN) {
                float2 v = make_float2(acc[mf][nf][0] + b0, acc[mf][nf][1] + b1);
                *(float2*)o = v;
            }
            if (m + 8 < NN) {
                float2 v = make_float2(acc[mf][nf][2] + b0, acc[mf][nf][3] + b1);
                *(float2*)(o + 8 * HH) = v;
            }
        }
    }
}

// ================= CSR build =================
__global__ void k_zero_deg() {
    int i = blockIdx.x * blockDim.x + threadIdx.x;
    if (i < NN) g_deg[i] = 0;
}
__global__ void k_hist(const int* __restrict__ dst) {
    int e = blockIdx.x * blockDim.x + threadIdx.x;
    if (e < EE) atomicAdd(&g_deg[dst[e]], 1);
}
__global__ __launch_bounds__(1024) void k_scan_local() {
    __shared__ int sh[1024];
    int i = blockIdx.x * 1024 + threadIdx.x;
    int v = (i < NN) ? g_deg[i] : 0;
    sh[threadIdx.x] = v;
    __syncthreads();
#pragma unroll
    for (int o = 1; o < 1024; o <<= 1) {
        int t = (threadIdx.x >= o) ? sh[threadIdx.x - o] : 0;
        __syncthreads();
        sh[threadIdx.x] += t;
        __syncthreads();
    }
    if (i < NN) g_tmp[i] = sh[threadIdx.x];
    if (threadIdx.x == 1023) g_bsum[blockIdx.x] = sh[1023];
}
__global__ void k_scan_bsum(int nb) {
    if (threadIdx.x == 0) {
        int s = 0;
        for (int b = 0; b < nb; b++) { s += g_bsum[b]; g_bsum[b] = s; }
    }
}
__global__ void k_scan_add() {
    int i = blockIdx.x * blockDim.x + threadIdx.x;
    if (i < NN) {
        int b = i >> 10;
        int incl = g_tmp[i] + (b > 0 ? g_bsum[b - 1] : 0);
        g_rowptr[i + 1] = incl;
        g_cursor[i] = incl - g_deg[i];
        if (i == 0) g_rowptr[0] = 0;
    }
}
__global__ void k_scatter(const int* __restrict__ src, const int* __restrict__ dst) {
    int e = blockIdx.x * blockDim.x + threadIdx.x;
    if (e < EE) {
        int pos = atomicAdd(&g_cursor[dst[e]], 1);
        g_csr_src[pos] = src[e];
    }
}

// ================= initial gates =================
__global__ __launch_bounds__(256) void k_prep(const float* __restrict__ attl,
                                              const float* __restrict__ attr) {
    int w = (blockIdx.x * blockDim.x + threadIdx.x) >> 5;
    if (w >= NN) return;
    int lane = threadIdx.x & 31;
    const float4* xr = (const float4*)(g_x0 + (size_t)w * HH);
    float4 v0 = xr[lane], v1 = xr[lane + 32];
    const float4* wl = (const float4*)attl;
    const float4* wr = (const float4*)attr;
    float sl = dot4(v0, wl[lane]) + dot4(v1, wl[lane + 32]);
    float sr = dot4(v0, wr[lane]) + dot4(v1, wr[lane + 32]);
    sl = warp_sum(sl);
    sr = warp_sum(sr);
    if (lane == 0) { g_al[0][w] = sl; g_ar[0][w] = sr; }
}

// ================= per-layer edge gates =================
__global__ __launch_bounds__(256) void k_gate(int slot) {
    int d = (blockIdx.x * blockDim.x + threadIdx.x) >> 5;
    if (d >= NN) return;
    int lane = threadIdx.x & 31;
    const float* al = g_al[slot];
    int beg = g_rowptr[d], end = g_rowptr[d + 1];
    float ard = g_ar[slot][d];
    for (int idx = beg + lane; idx < end; idx += 32) {
        int s = g_csr_src[idx];
        g_gate[idx] = 0.5f * tanhf(al[s] + ard);
    }
}

// ================= fused layer =================
template <int LIDX, bool LAST>
__global__ __launch_bounds__(256) void k_layer(
    const float* __restrict__ lng, const float* __restrict__ lnb,
    const float* __restrict__ attl, const float* __restrict__ attr,
    const float* __restrict__ Wl, const float* __restrict__ bl,
    float* __restrict__ emb_out, float* __restrict__ logp_out) {
    int d = (blockIdx.x * blockDim.x + threadIdx.x) >> 5;
    if (d >= NN) return;
    int lane = threadIdx.x & 31;

    const float* xin = (LIDX == 0) ? g_x0 : ((LIDX == 2) ? g_xb : g_xa);
    float* xout = (LIDX == 1) ? g_xb : g_xa;
    constexpr int SLOT_IN = (LIDX & 1);
    constexpr int SLOT_OUT = 1 - SLOT_IN;

    float aself = 0.5f * tanhf(g_al[SLOT_IN][d] + g_ar[SLOT_IN][d]);
    const float4* xd = (const float4*)(xin + (size_t)d * HH);
    float4 v0 = xd[lane], v1 = xd[lane + 32];
    float4 acc0 = make_float4(aself * v0.x, aself * v0.y, aself * v0.z, aself * v0.w);
    float4 acc1 = make_float4(aself * v1.x, aself * v1.y, aself * v1.z, aself * v1.w);

    int beg = g_rowptr[d], end = g_rowptr[d + 1];
    for (int base = beg; base < end; base += 32) {
        int idx = base + lane;
        int s = 0;
        float g = 0.f;
        if (idx < end) { s = g_csr_src[idx]; g = g_gate[idx]; }
        int cnt = min(32, end - base);
#pragma unroll 4
        for (int j = 0; j < cnt; j++) {
            int sj = __shfl_sync(0xffffffffu, s, j);
            float gj = __shfl_sync(0xffffffffu, g, j);
            const float4* xr = (const float4*)(xin + (size_t)sj * HH);
            float4 u0 = xr[lane], u1 = xr[lane + 32];
            acc0.x = fmaf(gj, u0.x, acc0.x); acc0.y = fmaf(gj, u0.y, acc0.y);
            acc0.z = fmaf(gj, u0.z, acc0.z); acc0.w = fmaf(gj, u0.w, acc0.w);
            acc1.x = fmaf(gj, u1.x, acc1.x); acc1.y = fmaf(gj, u1.y, acc1.y);
            acc1.z = fmaf(gj, u1.z, acc1.z); acc1.w = fmaf(gj, u1.w, acc1.w);
        }
    }

    const float4* x0r = (const float4*)(g_x0 + (size_t)d * HH);
    float4 z0 = x0r[lane], z1 = x0r[lane + 32];
    acc0.x = fmaf(0.1f, z0.x, acc0.x); acc0.y = fmaf(0.1f, z0.y, acc0.y);
    acc0.z = fmaf(0.1f, z0.z, acc0.z); acc0.w = fmaf(0.1f, z0.w, acc0.w);
    acc1.x = fmaf(0.1f, z1.x, acc1.x); acc1.y = fmaf(0.1f, z1.y, acc1.y);
    acc1.z = fmaf(0.1f, z1.z, acc1.z); acc1.w = fmaf(0.1f, z1.w, acc1.w);

    if (!LAST) {
        acc0.x = fmaxf(acc0.x, 0.f); acc0.y = fmaxf(acc0.y, 0.f);
        acc0.z = fmaxf(acc0.z, 0.f); acc0.w = fmaxf(acc0.w, 0.f);
        acc1.x = fmaxf(acc1.x, 0.f); acc1.y = fmaxf(acc1.y, 0.f);
        acc1.z = fmaxf(acc1.z, 0.f); acc1.w = fmaxf(acc1.w, 0.f);
        float sum = acc0.x + acc0.y + acc0.z + acc0.w + acc1.x + acc1.y + acc1.z + acc1.w;
        float sq = acc0.x * acc0.x + acc0.y * acc0.y + acc0.z * acc0.z + acc0.w * acc0.w +
                   acc1.x * acc1.x + acc1.y * acc1.y + acc1.z * acc1.z + acc1.w * acc1.w;
        sum = warp_sum(sum);
        sq = warp_sum(sq);
        float mu = sum * (1.f / HH);
        float var = sq * (1.f / HH) - mu * mu;
        float inv = rsqrtf(var + 1e-5f);
        const float4* gp = (const float4*)lng;
        const float4* bp = (const float4*)lnb;
        float4 gg0 = gp[lane], gg1 = gp[lane + 32];
        float4 bb0 = bp[lane], bb1 = bp[lane + 32];
        float4 y0 = make_float4((acc0.x - mu) * inv * gg0.x + bb0.x,
                                (acc0.y - mu) * inv * gg0.y + bb0.y,
                                (acc0.z - mu) * inv * gg0.z + bb0.z,
                                (acc0.w - mu) * inv * gg0.w + bb0.w);
        float4 y1 = make_float4((acc1.x - mu) * inv * gg1.x + bb1.x,
                                (acc1.y - mu) * inv * gg1.y + bb1.y,
                                (acc1.z - mu) * inv * gg1.z + bb1.z,
                                (acc1.w - mu) * inv * gg1.w + bb1.w);
        float4* xw = (float4*)(xout + (size_t)d * HH);
        xw[lane] = y0;
        xw[lane + 32] = y1;
        const float4* wl = (const float4*)attl;
        const float4* wr = (const float4*)attr;
        float sl = dot4(y0, wl[lane]) + dot4(y1, wl[lane + 32]);
        float sr = dot4(y0, wr[lane]) + dot4(y1, wr[lane + 32]);
        sl = warp_sum(sl);
        sr = warp_sum(sr);
        if (lane == 0) { g_al[SLOT_OUT][d] = sl; g_ar[SLOT_OUT][d] = sr; }
    } else {
        float e[CC];
#pragma unroll
        for (int c = 0; c < CC; c++) {
            const float4* wr = (const float4*)(Wl + c * HH);
            float p = dot4(acc0, wr[lane]) + dot4(acc1, wr[lane + 32]);
            e[c] = warp_sum(p);
        }
        if (lane == 0) {
            float val[CC];
            float m = -1e30f;
#pragma unroll
            for (int c = 0; c < CC; c++) {
                val[c] = e[c] + bl[c];
                m = fmaxf(m, val[c]);
            }
            float ssum = 0.f;
#pragma unroll
            for (int c = 0; c < CC; c++) ssum += expf(val[c] - m);
            float lse = m + logf(ssum);
#pragma unroll
            for (int c = 0; c < CC; c++) {
                if (emb_out) emb_out[(size_t)d * CC + c] = val[c];
                logp_out[(size_t)d * CC + c] = val[c] - lse;
            }
        }
    }
}

extern "C" void kernel_launch(void* const* d_in, const int* in_sizes, int n_in,
                              void* d_out, int out_size) {
    const float* x_in = (const float*)d_in[0];
    const int* ei     = (const int*)d_in[1];
    const float* Wi   = (const float*)d_in[2];
    const float* bi   = (const float*)d_in[3];
    const float* attl = (const float*)d_in[4];
    const float* attr = (const float*)d_in[5];
    const float* lng  = (const float*)d_in[6];
    const float* lnb  = (const float*)d_in[7];
    const float* Wl   = (const float*)d_in[8];
    const float* bl   = (const float*)d_in[9];
    float* out = (float*)d_out;

    const int* src = ei;
    const int* dst = ei + EE;

    // CSR build
    k_zero_deg<<<(NN + 255) / 256, 256>>>();
    k_hist<<<(EE + 255) / 256, 256>>>(dst);
    int nb = (NN + 1023) / 1024;
    k_scan_local<<<nb, 1024>>>();
    k_scan_bsum<<<1, 32>>>(nb);
    k_scan_add<<<(NN + 255) / 256, 256>>>();
    k_scatter<<<(EE + 255) / 256, 256>>>(src, dst);

    // split + tensor-core GEMM
    k_splitA<<<(MPAD * (KPAD / 4) + 255) / 256, 256>>>(x_in);
    k_splitB<<<(HH * (KPAD / 4) + 255) / 256, 256>>>(Wi);
    cudaFuncSetAttribute(k_gemm_tc, cudaFuncAttributeMaxDynamicSharedMemorySize,
                         2 * STAGE_B);
    dim3 gg(MTILES, HH / 128);
    k_gemm_tc<<<gg, 256, 2 * STAGE_B>>>(bi);

    int nodeBlocks = (NN + 7) / 8;
    k_prep<<<nodeBlocks, 256>>>(attl, attr);

    float* embp = nullptr;
    float* logp = out;
    if (out_size >= 2 * NN * CC) {
        embp = out;
        logp = out + (size_t)NN * CC;
    }

    k_gate<<<nodeBlocks, 256>>>(0);
    k_layer<0, false><<<nodeBlocks, 256>>>(lng + 0 * HH, lnb + 0 * HH,
                                           attl + 1 * HH, attr + 1 * HH,
                                           nullptr, nullptr, nullptr, nullptr);
    k_gate<<<nodeBlocks, 256>>>(1);
    k_layer<1, false><<<nodeBlocks, 256>>>(lng + 1 * HH, lnb + 1 * HH,
                                           attl + 2 * HH, attr + 2 * HH,
                                           nullptr, nullptr, nullptr, nullptr);
    k_gate<<<nodeBlocks, 256>>>(0);
    k_layer<2, false><<<nodeBlocks, 256>>>(lng + 2 * HH, lnb + 2 * HH,
                                           attl + 3 * HH, attr + 3 * HH,
                                           nullptr, nullptr, nullptr, nullptr);
    k_gate<<<nodeBlocks, 256>>>(1);
    k_layer<3, true><<<nodeBlocks, 256>>>(nullptr, nullptr, nullptr, nullptr,
                                          Wl, bl, embp, logp);
}

// round 9
// speedup vs baseline: 1.0086x; 1.0086x over previous
#include <cuda_runtime.h>
#include <stdint.h>
#include <math.h>

#define NN 50000
#define EE 800000
#define DIN 500
#define HH 256
#define CC 7

__device__ float g_x0[NN * HH];
__device__ float g_xa[NN * HH];
__device__ float g_xb[NN * HH];
__device__ float g_al[2][NN];
__device__ float g_ar[2][NN];
__device__ float g_Wt[DIN * HH];

__device__ int g_deg[NN];
__device__ int g_tmp[NN];
__device__ int g_bsum[64];
__device__ int g_rowptr[NN + 1];
__device__ int g_cursor[NN];
__device__ int g_csr_src[EE];

__device__ __forceinline__ float warp_sum(float v) {
#pragma unroll
    for (int o = 16; o; o >>= 1) v += __shfl_xor_sync(0xffffffffu, v, o);
    return v;
}

__device__ __forceinline__ float dot4(float4 a, float4 b) {
    return a.x * b.x + a.y * b.y + a.z * b.z + a.w * b.w;
}

// ---------------- W_init transpose ----------------
__global__ void k_transpose(const float* __restrict__ W) {
    int i = blockIdx.x * blockDim.x + threadIdx.x;
    if (i < DIN * HH) {
        int k = i / HH, h = i % HH;
        g_Wt[i] = W[h * DIN + k];
    }
}

// ---------------- SGEMM: g_x0 = x_in @ Wt + bias ----------------
__global__ __launch_bounds__(256) void k_gemm(const float* __restrict__ A,
                                              const float* __restrict__ bias) {
    __shared__ __align__(16) float As[8][128];
    __shared__ __align__(16) float Bs[8][128];
    int tid = threadIdx.x;
    int ty = tid >> 4, tx = tid & 15;
    int bm = blockIdx.x * 128, bn = blockIdx.y * 128;
    float acc[8][8] = {};
    int aRow = tid >> 1, aK4 = (tid & 1) * 4;
    int bK = tid >> 5, bH = (tid & 31) * 4;

    for (int kt = 0; kt < DIN; kt += 8) {
        float4 av = make_float4(0.f, 0.f, 0.f, 0.f);
        int m = bm + aRow;
        if (m < NN && (kt + aK4) < DIN)
            av = *(const float4*)(A + (size_t)m * DIN + kt + aK4);
        float4 bv = make_float4(0.f, 0.f, 0.f, 0.f);
        if ((kt + bK) < DIN)
            bv = *(const float4*)(g_Wt + (kt + bK) * HH + bn + bH);
        As[aK4 + 0][aRow] = av.x;
        As[aK4 + 1][aRow] = av.y;
        As[aK4 + 2][aRow] = av.z;
        As[aK4 + 3][aRow] = av.w;
        *(float4*)&Bs[bK][bH] = bv;
        __syncthreads();
#pragma unroll
        for (int kk = 0; kk < 8; kk++) {
            float4 a0 = *(const float4*)&As[kk][ty * 4];
            float4 a1 = *(const float4*)&As[kk][64 + ty * 4];
            float4 b0 = *(const float4*)&Bs[kk][tx * 4];
            float4 b1 = *(const float4*)&Bs[kk][64 + tx * 4];
            float a[8] = {a0.x, a0.y, a0.z, a0.w, a1.x, a1.y, a1.z, a1.w};
            float b[8] = {b0.x, b0.y, b0.z, b0.w, b1.x, b1.y, b1.z, b1.w};
#pragma unroll
            for (int i = 0; i < 8; i++)
#pragma unroll
                for (int j = 0; j < 8; j++)
                    acc[i][j] = fmaf(a[i], b[j], acc[i][j]);
        }
        __syncthreads();
    }

    float4 bias0 = *(const float4*)(bias + bn + tx * 4);
    float4 bias1 = *(const float4*)(bias + bn + 64 + tx * 4);
#pragma unroll
    for (int i = 0; i < 8; i++) {
        int m = bm + (i < 4 ? ty * 4 + i : 64 + ty * 4 + (i - 4));
        if (m >= NN) continue;
        float4 o0 = make_float4(acc[i][0] + bias0.x, acc[i][1] + bias0.y,
                                acc[i][2] + bias0.z, acc[i][3] + bias0.w);
        float4 o1 = make_float4(acc[i][4] + bias1.x, acc[i][5] + bias1.y,
                                acc[i][6] + bias1.z, acc[i][7] + bias1.w);
        *(float4*)(g_x0 + (size_t)m * HH + bn + tx * 4) = o0;
        *(float4*)(g_x0 + (size_t)m * HH + bn + 64 + tx * 4) = o1;
    }
}

// ---------------- CSR build ----------------
__global__ void k_zero_deg() {
    int i = blockIdx.x * blockDim.x + threadIdx.x;
    if (i < NN) g_deg[i] = 0;
}
__global__ void k_hist(const int* __restrict__ dst) {
    int e = blockIdx.x * blockDim.x + threadIdx.x;
    if (e < EE) atomicAdd(&g_deg[dst[e]], 1);
}
__global__ __launch_bounds__(1024) void k_scan_local() {
    __shared__ int sh[1024];
    int i = blockIdx.x * 1024 + threadIdx.x;
    int v = (i < NN) ? g_deg[i] : 0;
    sh[threadIdx.x] = v;
    __syncthreads();
#pragma unroll
    for (int o = 1; o < 1024; o <<= 1) {
        int t = (threadIdx.x >= o) ? sh[threadIdx.x - o] : 0;
        __syncthreads();
        sh[threadIdx.x] += t;
        __syncthreads();
    }
    if (i < NN) g_tmp[i] = sh[threadIdx.x];
    if (threadIdx.x == 1023) g_bsum[blockIdx.x] = sh[1023];
}
__global__ void k_scan_bsum(int nb) {
    if (threadIdx.x == 0) {
        int s = 0;
        for (int b = 0; b < nb; b++) { s += g_bsum[b]; g_bsum[b] = s; }
    }
}
__global__ void k_scan_add() {
    int i = blockIdx.x * blockDim.x + threadIdx.x;
    if (i < NN) {
        int b = i >> 10;
        int incl = g_tmp[i] + (b > 0 ? g_bsum[b - 1] : 0);
        g_rowptr[i + 1] = incl;
        g_cursor[i] = incl - g_deg[i];
        if (i == 0) g_rowptr[0] = 0;
    }
}
__global__ void k_scatter(const int* __restrict__ src, const int* __restrict__ dst) {
    int e = blockIdx.x * blockDim.x + threadIdx.x;
    if (e < EE) {
        int pos = atomicAdd(&g_cursor[dst[e]], 1);
        g_csr_src[pos] = src[e];
    }
}

// ---------------- initial gates (fp32 x0) ----------------
__global__ __launch_bounds__(256) void k_prep(const float* __restrict__ attl,
                                              const float* __restrict__ attr) {
    int w = (blockIdx.x * blockDim.x + threadIdx.x) >> 5;
    if (w >= NN) return;
    int lane = threadIdx.x & 31;
    const float4* xr = (const float4*)(g_x0 + (size_t)w * HH);
    float4 v0 = xr[lane * 2], v1 = xr[lane * 2 + 1];
    const float4* wl = (const float4*)attl;
    const float4* wr = (const float4*)attr;
    float sl = dot4(v0, wl[lane * 2]) + dot4(v1, wl[lane * 2 + 1]);
    float sr = dot4(v0, wr[lane * 2]) + dot4(v1, wr[lane * 2 + 1]);
    sl = warp_sum(sl);
    sr = warp_sum(sr);
    if (lane == 0) { g_al[0][w] = sl; g_ar[0][w] = sr; }
}

// ---------------- fused layer: inline gates + gather + node math ----------
// L0: x0 -> xa, slot0 -> slot1
// L1: xa -> xb, slot1 -> slot0
// L2: xb -> xa, slot0 -> slot1
// L3: xa -> head, slot1
template <int LIDX>
__global__ __launch_bounds__(256) void k_layer(
    const float* __restrict__ lng, const float* __restrict__ lnb,
    const float* __restrict__ attl, const float* __restrict__ attr,
    const float* __restrict__ Wl, const float* __restrict__ bl,
    float* __restrict__ emb_out, float* __restrict__ logp_out) {
    constexpr bool LAST = (LIDX == 3);
    constexpr int SLOT_IN = (LIDX & 1);
    constexpr int SLOT_OUT = 1 - SLOT_IN;

    int d = (blockIdx.x * blockDim.x + threadIdx.x) >> 5;
    if (d >= NN) return;
    int lane = threadIdx.x & 31;

    const float* xin = (LIDX == 0) ? g_x0 : ((LIDX == 2) ? g_xb : g_xa);
    float* xout = (LIDX == 1) ? g_xb : g_xa;

    const float* alv = g_al[SLOT_IN];
    float ard = g_ar[SLOT_IN][d];
    float aself = 0.5f * tanhf(alv[d] + ard);

    // self loop (lane owns cols [8*lane, 8*lane+8))
    const float4* xd = (const float4*)(xin + (size_t)d * HH);
    float4 v0 = xd[lane * 2], v1 = xd[lane * 2 + 1];
    float4 acc0 = make_float4(aself * v0.x, aself * v0.y, aself * v0.z, aself * v0.w);
    float4 acc1 = make_float4(aself * v1.x, aself * v1.y, aself * v1.z, aself * v1.w);

    // in-edges: warp-cooperative gather, gate computed inline
    int beg = g_rowptr[d], end = g_rowptr[d + 1];
    for (int base = beg; base < end; base += 32) {
        int idx = base + lane;
        int s = 0;
        float g = 0.f;
        if (idx < end) {
            s = g_csr_src[idx];
            g = 0.5f * tanhf(alv[s] + ard);
        }
        int cnt = min(32, end - base);
#pragma unroll 4
        for (int j = 0; j < cnt; j++) {
            int sj = __shfl_sync(0xffffffffu, s, j);
            float gj = __shfl_sync(0xffffffffu, g, j);
            const float4* xr = (const float4*)(xin + (size_t)sj * HH);
            float4 u0 = xr[lane * 2], u1 = xr[lane * 2 + 1];
            acc0.x = fmaf(gj, u0.x, acc0.x); acc0.y = fmaf(gj, u0.y, acc0.y);
            acc0.z = fmaf(gj, u0.z, acc0.z); acc0.w = fmaf(gj, u0.w, acc0.w);
            acc1.x = fmaf(gj, u1.x, acc1.x); acc1.y = fmaf(gj, u1.y, acc1.y);
            acc1.z = fmaf(gj, u1.z, acc1.z); acc1.w = fmaf(gj, u1.w, acc1.w);
        }
    }

    // + EPS * x0
    const float4* x0r = (const float4*)(g_x0 + (size_t)d * HH);
    float4 z0 = x0r[lane * 2], z1 = x0r[lane * 2 + 1];
    acc0.x = fmaf(0.1f, z0.x, acc0.x); acc0.y = fmaf(0.1f, z0.y, acc0.y);
    acc0.z = fmaf(0.1f, z0.z, acc0.z); acc0.w = fmaf(0.1f, z0.w, acc0.w);
    acc1.x = fmaf(0.1f, z1.x, acc1.x); acc1.y = fmaf(0.1f, z1.y, acc1.y);
    acc1.z = fmaf(0.1f, z1.z, acc1.z); acc1.w = fmaf(0.1f, z1.w, acc1.w);

    if (!LAST) {
        // relu
        acc0.x = fmaxf(acc0.x, 0.f); acc0.y = fmaxf(acc0.y, 0.f);
        acc0.z = fmaxf(acc0.z, 0.f); acc0.w = fmaxf(acc0.w, 0.f);
        acc1.x = fmaxf(acc1.x, 0.f); acc1.y = fmaxf(acc1.y, 0.f);
        acc1.z = fmaxf(acc1.z, 0.f); acc1.w = fmaxf(acc1.w, 0.f);
        // layernorm
        float sum = acc0.x + acc0.y + acc0.z + acc0.w + acc1.x + acc1.y + acc1.z + acc1.w;
        float sq = acc0.x * acc0.x + acc0.y * acc0.y + acc0.z * acc0.z + acc0.w * acc0.w +
                   acc1.x * acc1.x + acc1.y * acc1.y + acc1.z * acc1.z + acc1.w * acc1.w;
        sum = warp_sum(sum);
        sq = warp_sum(sq);
        float mu = sum * (1.f / HH);
        float var = sq * (1.f / HH) - mu * mu;
        float inv = rsqrtf(var + 1e-5f);
        const float4* gp = (const float4*)lng;
        const float4* bp = (const float4*)lnb;
        float4 gg0 = gp[lane * 2], gg1 = gp[lane * 2 + 1];
        float4 bb0 = bp[lane * 2], bb1 = bp[lane * 2 + 1];
        float4 y0 = make_float4((acc0.x - mu) * inv * gg0.x + bb0.x,
                                (acc0.y - mu) * inv * gg0.y + bb0.y,
                                (acc0.z - mu) * inv * gg0.z + bb0.z,
                                (acc0.w - mu) * inv * gg0.w + bb0.w);
        float4 y1 = make_float4((acc1.x - mu) * inv * gg1.x + bb1.x,
                                (acc1.y - mu) * inv * gg1.y + bb1.y,
                                (acc1.z - mu) * inv * gg1.z + bb1.z,
                                (acc1.w - mu) * inv * gg1.w + bb1.w);
        float4* xw = (float4*)(xout + (size_t)d * HH);
        xw[lane * 2] = y0;
        xw[lane * 2 + 1] = y1;
        // next-layer gates
        const float4* wl = (const float4*)attl;
        const float4* wr = (const float4*)attr;
        float sl = dot4(y0, wl[lane * 2]) + dot4(y1, wl[lane * 2 + 1]);
        float sr = dot4(y0, wr[lane * 2]) + dot4(y1, wr[lane * 2 + 1]);
        sl = warp_sum(sl);
        sr = warp_sum(sr);
        if (lane == 0) { g_al[SLOT_OUT][d] = sl; g_ar[SLOT_OUT][d] = sr; }
    } else {
        // final head + log_softmax
        float e[CC];
#pragma unroll
        for (int c = 0; c < CC; c++) {
            const float4* wr = (const float4*)(Wl + c * HH);
            float p = dot4(acc0, wr[lane * 2]) + dot4(acc1, wr[lane * 2 + 1]);
            e[c] = warp_sum(p);
        }
        if (lane == 0) {
            float val[CC];
            float m = -1e30f;
#pragma unroll
            for (int c = 0; c < CC; c++) {
                val[c] = e[c] + bl[c];
                m = fmaxf(m, val[c]);
            }
            float ssum = 0.f;
#pragma unroll
            for (int c = 0; c < CC; c++) ssum += expf(val[c] - m);
            float lse = m + logf(ssum);
#pragma unroll
            for (int c = 0; c < CC; c++) {
                if (emb_out) emb_out[(size_t)d * CC + c] = val[c];
                logp_out[(size_t)d * CC + c] = val[c] - lse;
            }
        }
    }
}

extern "C" void kernel_launch(void* const* d_in, const int* in_sizes, int n_in,
                              void* d_out, int out_size) {
    const float* x_in = (const float*)d_in[0];
    const int* ei     = (const int*)d_in[1];
    const float* Wi   = (const float*)d_in[2];
    const float* bi   = (const float*)d_in[3];
    const float* attl = (const float*)d_in[4];
    const float* attr = (const float*)d_in[5];
    const float* lng  = (const float*)d_in[6];
    const float* lnb  = (const float*)d_in[7];
    const float* Wl   = (const float*)d_in[8];
    const float* bl   = (const float*)d_in[9];
    float* out = (float*)d_out;

    const int* src = ei;
    const int* dst = ei + EE;

    // CSR build
    k_zero_deg<<<(NN + 255) / 256, 256>>>();
    k_hist<<<(EE + 255) / 256, 256>>>(dst);
    int nb = (NN + 1023) / 1024;
    k_scan_local<<<nb, 1024>>>();
    k_scan_bsum<<<1, 32>>>(nb);
    k_scan_add<<<(NN + 255) / 256, 256>>>();
    k_scatter<<<(EE + 255) / 256, 256>>>(src, dst);

    // init GEMM (FFMA)
    k_transpose<<<(DIN * HH + 255) / 256, 256>>>(Wi);
    dim3 gg((NN + 127) / 128, HH / 128);
    k_gemm<<<gg, 256>>>(x_in, bi);

    int nodeBlocks = (NN + 7) / 8;
    k_prep<<<nodeBlocks, 256>>>(attl, attr);

    float* embp = nullptr;
    float* logp = out;
    if (out_size >= 2 * NN * CC) {
        embp = out;
        logp = out + (size_t)NN * CC;
    }

    k_layer<0><<<nodeBlocks, 256>>>(lng + 0 * HH, lnb + 0 * HH,
                                    attl + 1 * HH, attr + 1 * HH,
                                    nullptr, nullptr, nullptr, nullptr);
    k_layer<1><<<nodeBlocks, 256>>>(lng + 1 * HH, lnb + 1 * HH,
                                    attl + 2 * HH, attr + 2 * HH,
                                    nullptr, nullptr, nullptr, nullptr);
    k_layer<2><<<nodeBlocks, 256>>>(lng + 2 * HH, lnb + 2 * HH,
                                    attl + 3 * HH, attr + 3 * HH,
                                    nullptr, nullptr, nullptr, nullptr);
    k_layer<3><<<nodeBlocks, 256>>>(nullptr, nullptr, nullptr, nullptr,
                                    Wl, bl, embp, logp);
}

// round 10
// speedup vs baseline: 1.1189x; 1.1093x over previous
#include <cuda_runtime.h>
#include <stdint.h>
#include <math.h>

#define NN 50000
#define EE 800000
#define DIN 500
#define HH 256
#define CC 7

__device__ float g_x0[NN * HH];
__device__ float g_xa[NN * HH];
__device__ float g_xb[NN * HH];
__device__ float g_al[2][NN];
__device__ float g_ar[2][NN];
__device__ float g_Wt[DIN * HH];

__device__ int g_deg[NN];
__device__ int g_tmp[NN];
__device__ int g_bsum[64];
__device__ int g_rowptr[NN + 1];
__device__ int g_cursor[NN];
__device__ int g_csr_src[EE];
__device__ float g_gate[EE];

__device__ __forceinline__ float warp_sum(float v) {
#pragma unroll
    for (int o = 16; o; o >>= 1) v += __shfl_xor_sync(0xffffffffu, v, o);
    return v;
}

__device__ __forceinline__ float dot4(float4 a, float4 b) {
    return a.x * b.x + a.y * b.y + a.z * b.z + a.w * b.w;
}

__device__ __forceinline__ float2 u2f2(unsigned long long v) {
    return make_float2(__uint_as_float((unsigned)v),
                       __uint_as_float((unsigned)(v >> 32)));
}

// ---------------- W_init transpose ----------------
__global__ void k_transpose(const float* __restrict__ W) {
    int i = blockIdx.x * blockDim.x + threadIdx.x;
    if (i < DIN * HH) {
        int k = i / HH, h = i % HH;
        g_Wt[i] = W[h * DIN + k];
    }
}

// ---------------- SGEMM with packed fma.rn.f32x2 ----------------
__global__ __launch_bounds__(256) void k_gemm(const float* __restrict__ A,
                                              const float* __restrict__ bias) {
    __shared__ __align__(16) float As[8][128];
    __shared__ __align__(16) float Bs[8][128];
    int tid = threadIdx.x;
    int ty = tid >> 4, tx = tid & 15;
    int bm = blockIdx.x * 128, bn = blockIdx.y * 128;
    // acc2[i][j] = packed pair of output cols {2j, 2j+1} within this thread's 8 cols
    unsigned long long acc2[8][4];
#pragma unroll
    for (int i = 0; i < 8; i++)
#pragma unroll
        for (int j = 0; j < 4; j++) acc2[i][j] = 0ull;

    int aRow = tid >> 1, aK4 = (tid & 1) * 4;
    int bK = tid >> 5, bH = (tid & 31) * 4;

    for (int kt = 0; kt < DIN; kt += 8) {
        float4 av = make_float4(0.f, 0.f, 0.f, 0.f);
        int m = bm + aRow;
        if (m < NN && (kt + aK4) < DIN)
            av = *(const float4*)(A + (size_t)m * DIN + kt + aK4);
        float4 bv = make_float4(0.f, 0.f, 0.f, 0.f);
        if ((kt + bK) < DIN)
            bv = *(const float4*)(g_Wt + (kt + bK) * HH + bn + bH);
        As[aK4 + 0][aRow] = av.x;
        As[aK4 + 1][aRow] = av.y;
        As[aK4 + 2][aRow] = av.z;
        As[aK4 + 3][aRow] = av.w;
        *(float4*)&Bs[bK][bH] = bv;
        __syncthreads();
#pragma unroll
        for (int kk = 0; kk < 8; kk++) {
            float4 a0 = *(const float4*)&As[kk][ty * 4];
            float4 a1 = *(const float4*)&As[kk][64 + ty * 4];
            // B pairs packed for free by 64-bit reinterpretation of the row
            ulonglong2 bq0 = *(const ulonglong2*)&Bs[kk][tx * 4];
            ulonglong2 bq1 = *(const ulonglong2*)&Bs[kk][64 + tx * 4];
            unsigned long long b2[4] = {bq0.x, bq0.y, bq1.x, bq1.y};
            float a[8] = {a0.x, a0.y, a0.z, a0.w, a1.x, a1.y, a1.z, a1.w};
            unsigned long long ad[8];
#pragma unroll
            for (int i = 0; i < 8; i++)
                asm("mov.b64 %0, {%1, %1};"
                    : "=l"(ad[i]) : "r"(__float_as_uint(a[i])));
#pragma unroll
            for (int i = 0; i < 8; i++)
#pragma unroll
                for (int j = 0; j < 4; j++)
                    asm("fma.rn.f32x2 %0, %1, %2, %0;"
                        : "+l"(acc2[i][j]) : "l"(ad[i]), "l"(b2[j]));
        }
        __syncthreads();
    }

    float4 bias0 = *(const float4*)(bias + bn + tx * 4);
    float4 bias1 = *(const float4*)(bias + bn + 64 + tx * 4);
#pragma unroll
    for (int i = 0; i < 8; i++) {
        int m = bm + (i < 4 ? ty * 4 + i : 64 + ty * 4 + (i - 4));
        if (m >= NN) continue;
        float2 p0 = u2f2(acc2[i][0]), p1 = u2f2(acc2[i][1]);
        float2 p2 = u2f2(acc2[i][2]), p3 = u2f2(acc2[i][3]);
        float4 o0 = make_float4(p0.x + bias0.x, p0.y + bias0.y,
                                p1.x + bias0.z, p1.y + bias0.w);
        float4 o1 = make_float4(p2.x + bias1.x, p2.y + bias1.y,
                                p3.x + bias1.z, p3.y + bias1.w);
        *(float4*)(g_x0 + (size_t)m * HH + bn + tx * 4) = o0;
        *(float4*)(g_x0 + (size_t)m * HH + bn + 64 + tx * 4) = o1;
    }
}

// ---------------- CSR build ----------------
__global__ void k_zero_deg() {
    int i = blockIdx.x * blockDim.x + threadIdx.x;
    if (i < NN) g_deg[i] = 0;
}
__global__ void k_hist(const int* __restrict__ dst) {
    int e = blockIdx.x * blockDim.x + threadIdx.x;
    if (e < EE) atomicAdd(&g_deg[dst[e]], 1);
}
__global__ __launch_bounds__(1024) void k_scan_local() {
    __shared__ int sh[1024];
    int i = blockIdx.x * 1024 + threadIdx.x;
    int v = (i < NN) ? g_deg[i] : 0;
    sh[threadIdx.x] = v;
    __syncthreads();
#pragma unroll
    for (int o = 1; o < 1024; o <<= 1) {
        int t = (threadIdx.x >= o) ? sh[threadIdx.x - o] : 0;
        __syncthreads();
        sh[threadIdx.x] += t;
        __syncthreads();
    }
    if (i < NN) g_tmp[i] = sh[threadIdx.x];
    if (threadIdx.x == 1023) g_bsum[blockIdx.x] = sh[1023];
}
__global__ void k_scan_bsum(int nb) {
    if (threadIdx.x == 0) {
        int s = 0;
        for (int b = 0; b < nb; b++) { s += g_bsum[b]; g_bsum[b] = s; }
    }
}
__global__ void k_scan_add() {
    int i = blockIdx.x * blockDim.x + threadIdx.x;
    if (i < NN) {
        int b = i >> 10;
        int incl = g_tmp[i] + (b > 0 ? g_bsum[b - 1] : 0);
        g_rowptr[i + 1] = incl;
        g_cursor[i] = incl - g_deg[i];
        if (i == 0) g_rowptr[0] = 0;
    }
}
__global__ void k_scatter(const int* __restrict__ src, const int* __restrict__ dst) {
    int e = blockIdx.x * blockDim.x + threadIdx.x;
    if (e < EE) {
        int pos = atomicAdd(&g_cursor[dst[e]], 1);
        g_csr_src[pos] = src[e];
    }
}

// ---------------- initial gates ----------------
__global__ __launch_bounds__(256) void k_prep(const float* __restrict__ attl,
                                              const float* __restrict__ attr) {
    int w = (blockIdx.x * blockDim.x + threadIdx.x) >> 5;
    if (w >= NN) return;
    int lane = threadIdx.x & 31;
    const float4* xr = (const float4*)(g_x0 + (size_t)w * HH);
    float4 v0 = xr[lane], v1 = xr[lane + 32];
    const float4* wl = (const float4*)attl;
    const float4* wr = (const float4*)attr;
    float sl = dot4(v0, wl[lane]) + dot4(v1, wl[lane + 32]);
    float sr = dot4(v0, wr[lane]) + dot4(v1, wr[lane + 32]);
    sl = warp_sum(sl);
    sr = warp_sum(sr);
    if (lane == 0) { g_al[0][w] = sl; g_ar[0][w] = sr; }
}

// ---------------- per-layer edge gates ----------------
__global__ __launch_bounds__(256) void k_gate(int slot) {
    int d = (blockIdx.x * blockDim.x + threadIdx.x) >> 5;
    if (d >= NN) return;
    int lane = threadIdx.x & 31;
    const float* al = g_al[slot];
    int beg = g_rowptr[d], end = g_rowptr[d + 1];
    float ard = g_ar[slot][d];
    for (int idx = beg + lane; idx < end; idx += 32) {
        int s = g_csr_src[idx];
        g_gate[idx] = 0.5f * tanhf(al[s] + ard);
    }
}

// ---------------- fused layer (R3-proven mapping: lane, lane+32) ----------
template <int LIDX, bool LAST>
__global__ __launch_bounds__(256) void k_layer(
    const float* __restrict__ lng, const float* __restrict__ lnb,
    const float* __restrict__ attl, const float* __restrict__ attr,
    const float* __restrict__ Wl, const float* __restrict__ bl,
    float* __restrict__ emb_out, float* __restrict__ logp_out) {
    int d = (blockIdx.x * blockDim.x + threadIdx.x) >> 5;
    if (d >= NN) return;
    int lane = threadIdx.x & 31;

    const float* xin = (LIDX == 0) ? g_x0 : ((LIDX == 2) ? g_xb : g_xa);
    float* xout = (LIDX == 1) ? g_xb : g_xa;
    constexpr int SLOT_IN = (LIDX & 1);
    constexpr int SLOT_OUT = 1 - SLOT_IN;

    float aself = 0.5f * tanhf(g_al[SLOT_IN][d] + g_ar[SLOT_IN][d]);
    const float4* xd = (const float4*)(xin + (size_t)d * HH);
    float4 v0 = xd[lane], v1 = xd[lane + 32];
    float4 acc0 = make_float4(aself * v0.x, aself * v0.y, aself * v0.z, aself * v0.w);
    float4 acc1 = make_float4(aself * v1.x, aself * v1.y, aself * v1.z, aself * v1.w);

    int beg = g_rowptr[d], end = g_rowptr[d + 1];
    for (int base = beg; base < end; base += 32) {
        int idx = base + lane;
        int s = 0;
        float g = 0.f;
        if (idx < end) { s = g_csr_src[idx]; g = g_gate[idx]; }
        int cnt = min(32, end - base);
#pragma unroll 4
        for (int j = 0; j < cnt; j++) {
            int sj = __shfl_sync(0xffffffffu, s, j);
            float gj = __shfl_sync(0xffffffffu, g, j);
            const float4* xr = (const float4*)(xin + (size_t)sj * HH);
            float4 u0 = xr[lane], u1 = xr[lane + 32];
            acc0.x = fmaf(gj, u0.x, acc0.x); acc0.y = fmaf(gj, u0.y, acc0.y);
            acc0.z = fmaf(gj, u0.z, acc0.z); acc0.w = fmaf(gj, u0.w, acc0.w);
            acc1.x = fmaf(gj, u1.x, acc1.x); acc1.y = fmaf(gj, u1.y, acc1.y);
            acc1.z = fmaf(gj, u1.z, acc1.z); acc1.w = fmaf(gj, u1.w, acc1.w);
        }
    }

    const float4* x0r = (const float4*)(g_x0 + (size_t)d * HH);
    float4 z0 = x0r[lane], z1 = x0r[lane + 32];
    acc0.x = fmaf(0.1f, z0.x, acc0.x); acc0.y = fmaf(0.1f, z0.y, acc0.y);
    acc0.z = fmaf(0.1f, z0.z, acc0.z); acc0.w = fmaf(0.1f, z0.w, acc0.w);
    acc1.x = fmaf(0.1f, z1.x, acc1.x); acc1.y = fmaf(0.1f, z1.y, acc1.y);
    acc1.z = fmaf(0.1f, z1.z, acc1.z); acc1.w = fmaf(0.1f, z1.w, acc1.w);

    if (!LAST) {
        acc0.x = fmaxf(acc0.x, 0.f); acc0.y = fmaxf(acc0.y, 0.f);
        acc0.z = fmaxf(acc0.z, 0.f); acc0.w = fmaxf(acc0.w, 0.f);
        acc1.x = fmaxf(acc1.x, 0.f); acc1.y = fmaxf(acc1.y, 0.f);
        acc1.z = fmaxf(acc1.z, 0.f); acc1.w = fmaxf(acc1.w, 0.f);
        float sum = acc0.x + acc0.y + acc0.z + acc0.w + acc1.x + acc1.y + acc1.z + acc1.w;
        float sq = acc0.x * acc0.x + acc0.y * acc0.y + acc0.z * acc0.z + acc0.w * acc0.w +
                   acc1.x * acc1.x + acc1.y * acc1.y + acc1.z * acc1.z + acc1.w * acc1.w;
        sum = warp_sum(sum);
        sq = warp_sum(sq);
        float mu = sum * (1.f / HH);
        float var = sq * (1.f / HH) - mu * mu;
        float inv = rsqrtf(var + 1e-5f);
        const float4* gp = (const float4*)lng;
        const float4* bp = (const float4*)lnb;
        float4 gg0 = gp[lane], gg1 = gp[lane + 32];
        float4 bb0 = bp[lane], bb1 = bp[lane + 32];
        float4 y0 = make_float4((acc0.x - mu) * inv * gg0.x + bb0.x,
                                (acc0.y - mu) * inv * gg0.y + bb0.y,
                                (acc0.z - mu) * inv * gg0.z + bb0.z,
                                (acc0.w - mu) * inv * gg0.w + bb0.w);
        float4 y1 = make_float4((acc1.x - mu) * inv * gg1.x + bb1.x,
                                (acc1.y - mu) * inv * gg1.y + bb1.y,
                                (acc1.z - mu) * inv * gg1.z + bb1.z,
                                (acc1.w - mu) * inv * gg1.w + bb1.w);
        float4* xw = (float4*)(xout + (size_t)d * HH);
        xw[lane] = y0;
        xw[lane + 32] = y1;
        const float4* wl = (const float4*)attl;
        const float4* wr = (const float4*)attr;
        float sl = dot4(y0, wl[lane]) + dot4(y1, wl[lane + 32]);
        float sr = dot4(y0, wr[lane]) + dot4(y1, wr[lane + 32]);
        sl = warp_sum(sl);
        sr = warp_sum(sr);
        if (lane == 0) { g_al[SLOT_OUT][d] = sl; g_ar[SLOT_OUT][d] = sr; }
    } else {
        float e[CC];
#pragma unroll
        for (int c = 0; c < CC; c++) {
            const float4* wr = (const float4*)(Wl + c * HH);
            float p = dot4(acc0, wr[lane]) + dot4(acc1, wr[lane + 32]);
            e[c] = warp_sum(p);
        }
        if (lane == 0) {
            float val[CC];
            float m = -1e30f;
#pragma unroll
            for (int c = 0; c < CC; c++) {
                val[c] = e[c] + bl[c];
                m = fmaxf(m, val[c]);
            }
            float ssum = 0.f;
#pragma unroll
            for (int c = 0; c < CC; c++) ssum += expf(val[c] - m);
            float lse = m + logf(ssum);
#pragma unroll
            for (int c = 0; c < CC; c++) {
                if (emb_out) emb_out[(size_t)d * CC + c] = val[c];
                logp_out[(size_t)d * CC + c] = val[c] - lse;
            }
        }
    }
}

extern "C" void kernel_launch(void* const* d_in, const int* in_sizes, int n_in,
                              void* d_out, int out_size) {
    const float* x_in = (const float*)d_in[0];
    const int* ei     = (const int*)d_in[1];
    const float* Wi   = (const float*)d_in[2];
    const float* bi   = (const float*)d_in[3];
    const float* attl = (const float*)d_in[4];
    const float* attr = (const float*)d_in[5];
    const float* lng  = (const float*)d_in[6];
    const float* lnb  = (const float*)d_in[7];
    const float* Wl   = (const float*)d_in[8];
    const float* bl   = (const float*)d_in[9];
    float* out = (float*)d_out;

    const int* src = ei;
    const int* dst = ei + EE;

    // CSR build
    k_zero_deg<<<(NN + 255) / 256, 256>>>();
    k_hist<<<(EE + 255) / 256, 256>>>(dst);
    int nb = (NN + 1023) / 1024;
    k_scan_local<<<nb, 1024>>>();
    k_scan_bsum<<<1, 32>>>(nb);
    k_scan_add<<<(NN + 255) / 256, 256>>>();
    k_scatter<<<(EE + 255) / 256, 256>>>(src, dst);

    // init GEMM (f32x2 FFMA2)
    k_transpose<<<(DIN * HH + 255) / 256, 256>>>(Wi);
    dim3 gg((NN + 127) / 128, HH / 128);
    k_gemm<<<gg, 256>>>(x_in, bi);

    int nodeBlocks = (NN + 7) / 8;
    k_prep<<<nodeBlocks, 256>>>(attl, attr);

    float* embp = nullptr;
    float* logp = out;
    if (out_size >= 2 * NN * CC) {
        embp = out;
        logp = out + (size_t)NN * CC;
    }

    k_gate<<<nodeBlocks, 256>>>(0);
    k_layer<0, false><<<nodeBlocks, 256>>>(lng + 0 * HH, lnb + 0 * HH,
                                           attl + 1 * HH, attr + 1 * HH,
                                           nullptr, nullptr, nullptr, nullptr);
    k_gate<<<nodeBlocks, 256>>>(1);
    k_layer<1, false><<<nodeBlocks, 256>>>(lng + 1 * HH, lnb + 1 * HH,
                                           attl + 2 * HH, attr + 2 * HH,
                                           nullptr, nullptr, nullptr, nullptr);
    k_gate<<<nodeBlocks, 256>>>(0);
    k_layer<2, false><<<nodeBlocks, 256>>>(lng + 2 * HH, lnb + 2 * HH,
                                           attl + 3 * HH, attr + 3 * HH,
                                           nullptr, nullptr, nullptr, nullptr);
    k_gate<<<nodeBlocks, 256>>>(1);
    k_layer<3, true><<<nodeBlocks, 256>>>(nullptr, nullptr, nullptr, nullptr,
                                          Wl, bl, embp, logp);
}

// round 11
// speedup vs baseline: 1.2052x; 1.0771x over previous
#include <cuda_runtime.h>
#include <stdint.h>
#include <math.h>

#define NN 50000
#define EE 800000
#define DIN 500
#define HH 256
#define CC 7

__device__ float g_x0[NN * HH];
__device__ float g_xa[NN * HH];
__device__ float g_xb[NN * HH];
__device__ float g_al[2][NN];
__device__ float g_ar[2][NN];
__device__ float g_Wt[DIN * HH];

__device__ int g_deg[NN];
__device__ int g_tmp[NN];
__device__ int g_bsum[64];
__device__ int g_rowptr[NN + 1];
__device__ int g_cursor[NN];
__device__ int g_csr_src[EE];

__device__ __forceinline__ float warp_sum(float v) {
#pragma unroll
    for (int o = 16; o; o >>= 1) v += __shfl_xor_sync(0xffffffffu, v, o);
    return v;
}

__device__ __forceinline__ float dot4(float4 a, float4 b) {
    return a.x * b.x + a.y * b.y + a.z * b.z + a.w * b.w;
}

__device__ __forceinline__ float2 u2f2(unsigned long long v) {
    return make_float2(__uint_as_float((unsigned)v),
                       __uint_as_float((unsigned)(v >> 32)));
}

// ---------------- W_init transpose ----------------
__global__ void k_transpose(const float* __restrict__ W) {
    int i = blockIdx.x * blockDim.x + threadIdx.x;
    if (i < DIN * HH) {
        int k = i / HH, h = i % HH;
        g_Wt[i] = W[h * DIN + k];
    }
}

// ---------------- SGEMM with packed fma.rn.f32x2 (R10-proven) ----------------
__global__ __launch_bounds__(256) void k_gemm(const float* __restrict__ A,
                                              const float* __restrict__ bias) {
    __shared__ __align__(16) float As[8][128];
    __shared__ __align__(16) float Bs[8][128];
    int tid = threadIdx.x;
    int ty = tid >> 4, tx = tid & 15;
    int bm = blockIdx.x * 128, bn = blockIdx.y * 128;
    unsigned long long acc2[8][4];
#pragma unroll
    for (int i = 0; i < 8; i++)
#pragma unroll
        for (int j = 0; j < 4; j++) acc2[i][j] = 0ull;

    int aRow = tid >> 1, aK4 = (tid & 1) * 4;
    int bK = tid >> 5, bH = (tid & 31) * 4;

    for (int kt = 0; kt < DIN; kt += 8) {
        float4 av = make_float4(0.f, 0.f, 0.f, 0.f);
        int m = bm + aRow;
        if (m < NN && (kt + aK4) < DIN)
            av = *(const float4*)(A + (size_t)m * DIN + kt + aK4);
        float4 bv = make_float4(0.f, 0.f, 0.f, 0.f);
        if ((kt + bK) < DIN)
            bv = *(const float4*)(g_Wt + (kt + bK) * HH + bn + bH);
        As[aK4 + 0][aRow] = av.x;
        As[aK4 + 1][aRow] = av.y;
        As[aK4 + 2][aRow] = av.z;
        As[aK4 + 3][aRow] = av.w;
        *(float4*)&Bs[bK][bH] = bv;
        __syncthreads();
#pragma unroll
        for (int kk = 0; kk < 8; kk++) {
            float4 a0 = *(const float4*)&As[kk][ty * 4];
            float4 a1 = *(const float4*)&As[kk][64 + ty * 4];
            ulonglong2 bq0 = *(const ulonglong2*)&Bs[kk][tx * 4];
            ulonglong2 bq1 = *(const ulonglong2*)&Bs[kk][64 + tx * 4];
            unsigned long long b2[4] = {bq0.x, bq0.y, bq1.x, bq1.y};
            float a[8] = {a0.x, a0.y, a0.z, a0.w, a1.x, a1.y, a1.z, a1.w};
            unsigned long long ad[8];
#pragma unroll
            for (int i = 0; i < 8; i++)
                asm("mov.b64 %0, {%1, %1};"
                    : "=l"(ad[i]) : "r"(__float_as_uint(a[i])));
#pragma unroll
            for (int i = 0; i < 8; i++)
#pragma unroll
                for (int j = 0; j < 4; j++)
                    asm("fma.rn.f32x2 %0, %1, %2, %0;"
                        : "+l"(acc2[i][j]) : "l"(ad[i]), "l"(b2[j]));
        }
        __syncthreads();
    }

    float4 bias0 = *(const float4*)(bias + bn + tx * 4);
    float4 bias1 = *(const float4*)(bias + bn + 64 + tx * 4);
#pragma unroll
    for (int i = 0; i < 8; i++) {
        int m = bm + (i < 4 ? ty * 4 + i : 64 + ty * 4 + (i - 4));
        if (m >= NN) continue;
        float2 p0 = u2f2(acc2[i][0]), p1 = u2f2(acc2[i][1]);
        float2 p2 = u2f2(acc2[i][2]), p3 = u2f2(acc2[i][3]);
        float4 o0 = make_float4(p0.x + bias0.x, p0.y + bias0.y,
                                p1.x + bias0.z, p1.y + bias0.w);
        float4 o1 = make_float4(p2.x + bias1.x, p2.y + bias1.y,
                                p3.x + bias1.z, p3.y + bias1.w);
        *(float4*)(g_x0 + (size_t)m * HH + bn + tx * 4) = o0;
        *(float4*)(g_x0 + (size_t)m * HH + bn + 64 + tx * 4) = o1;
    }
}

// ---------------- CSR build ----------------
__global__ void k_zero_deg() {
    int i = blockIdx.x * blockDim.x + threadIdx.x;
    if (i < NN) g_deg[i] = 0;
}
__global__ void k_hist(const int* __restrict__ dst) {
    int e = blockIdx.x * blockDim.x + threadIdx.x;
    if (e < EE) atomicAdd(&g_deg[dst[e]], 1);
}
__global__ __launch_bounds__(1024) void k_scan_local() {
    __shared__ int sh[1024];
    int i = blockIdx.x * 1024 + threadIdx.x;
    int v = (i < NN) ? g_deg[i] : 0;
    sh[threadIdx.x] = v;
    __syncthreads();
#pragma unroll
    for (int o = 1; o < 1024; o <<= 1) {
        int t = (threadIdx.x >= o) ? sh[threadIdx.x - o] : 0;
        __syncthreads();
        sh[threadIdx.x] += t;
        __syncthreads();
    }
    if (i < NN) g_tmp[i] = sh[threadIdx.x];
    if (threadIdx.x == 1023) g_bsum[blockIdx.x] = sh[1023];
}
__global__ void k_scan_bsum(int nb) {
    if (threadIdx.x == 0) {
        int s = 0;
        for (int b = 0; b < nb; b++) { s += g_bsum[b]; g_bsum[b] = s; }
    }
}
__global__ void k_scan_add() {
    int i = blockIdx.x * blockDim.x + threadIdx.x;
    if (i < NN) {
        int b = i >> 10;
        int incl = g_tmp[i] + (b > 0 ? g_bsum[b - 1] : 0);
        g_rowptr[i + 1] = incl;
        g_cursor[i] = incl - g_deg[i];
        if (i == 0) g_rowptr[0] = 0;
    }
}
__global__ void k_scatter(const int* __restrict__ src, const int* __restrict__ dst) {
    int e = blockIdx.x * blockDim.x + threadIdx.x;
    if (e < EE) {
        int pos = atomicAdd(&g_cursor[dst[e]], 1);
        g_csr_src[pos] = src[e];
    }
}

// ---------------- initial gates ----------------
__global__ __launch_bounds__(256) void k_prep(const float* __restrict__ attl,
                                              const float* __restrict__ attr) {
    int w = (blockIdx.x * blockDim.x + threadIdx.x) >> 5;
    if (w >= NN) return;
    int lane = threadIdx.x & 31;
    const float4* xr = (const float4*)(g_x0 + (size_t)w * HH);
    float4 v0 = xr[lane], v1 = xr[lane + 32];
    const float4* wl = (const float4*)attl;
    const float4* wr = (const float4*)attr;
    float sl = dot4(v0, wl[lane]) + dot4(v1, wl[lane + 32]);
    float sr = dot4(v0, wr[lane]) + dot4(v1, wr[lane + 32]);
    sl = warp_sum(sl);
    sr = warp_sum(sr);
    if (lane == 0) { g_al[0][w] = sl; g_ar[0][w] = sr; }
}

// ---------------- fused layer: inline gates, R3 lane mapping ----------
// L0: x0 -> xa, slot0 -> slot1
// L1: xa -> xb, slot1 -> slot0
// L2: xb -> xa, slot0 -> slot1
// L3: xa -> head, slot1
template <int LIDX, bool LAST>
__global__ __launch_bounds__(256) void k_layer(
    const float* __restrict__ lng, const float* __restrict__ lnb,
    const float* __restrict__ attl, const float* __restrict__ attr,
    const float* __restrict__ Wl, const float* __restrict__ bl,
    float* __restrict__ emb_out, float* __restrict__ logp_out) {
    int d = (blockIdx.x * blockDim.x + threadIdx.x) >> 5;
    if (d >= NN) return;
    int lane = threadIdx.x & 31;

    const float* xin = (LIDX == 0) ? g_x0 : ((LIDX == 2) ? g_xb : g_xa);
    float* xout = (LIDX == 1) ? g_xb : g_xa;
    constexpr int SLOT_IN = (LIDX & 1);
    constexpr int SLOT_OUT = 1 - SLOT_IN;

    const float* alv = g_al[SLOT_IN];
    float ard = g_ar[SLOT_IN][d];
    float aself = 0.5f * tanhf(alv[d] + ard);

    const float4* xd = (const float4*)(xin + (size_t)d * HH);
    float4 v0 = xd[lane], v1 = xd[lane + 32];
    float4 acc0 = make_float4(aself * v0.x, aself * v0.y, aself * v0.z, aself * v0.w);
    float4 acc1 = make_float4(aself * v1.x, aself * v1.y, aself * v1.z, aself * v1.w);

    int beg = g_rowptr[d], end = g_rowptr[d + 1];
    for (int base = beg; base < end; base += 32) {
        int idx = base + lane;
        int s = 0;
        float g = 0.f;
        if (idx < end) {
            s = g_csr_src[idx];
            g = 0.5f * tanhf(alv[s] + ard);
        }
        int cnt = min(32, end - base);
#pragma unroll 4
        for (int j = 0; j < cnt; j++) {
            int sj = __shfl_sync(0xffffffffu, s, j);
            float gj = __shfl_sync(0xffffffffu, g, j);
            const float4* xr = (const float4*)(xin + (size_t)sj * HH);
            float4 u0 = xr[lane], u1 = xr[lane + 32];
            acc0.x = fmaf(gj, u0.x, acc0.x); acc0.y = fmaf(gj, u0.y, acc0.y);
            acc0.z = fmaf(gj, u0.z, acc0.z); acc0.w = fmaf(gj, u0.w, acc0.w);
            acc1.x = fmaf(gj, u1.x, acc1.x); acc1.y = fmaf(gj, u1.y, acc1.y);
            acc1.z = fmaf(gj, u1.z, acc1.z); acc1.w = fmaf(gj, u1.w, acc1.w);
        }
    }

    const float4* x0r = (const float4*)(g_x0 + (size_t)d * HH);
    float4 z0 = x0r[lane], z1 = x0r[lane + 32];
    acc0.x = fmaf(0.1f, z0.x, acc0.x); acc0.y = fmaf(0.1f, z0.y, acc0.y);
    acc0.z = fmaf(0.1f, z0.z, acc0.z); acc0.w = fmaf(0.1f, z0.w, acc0.w);
    acc1.x = fmaf(0.1f, z1.x, acc1.x); acc1.y = fmaf(0.1f, z1.y, acc1.y);
    acc1.z = fmaf(0.1f, z1.z, acc1.z); acc1.w = fmaf(0.1f, z1.w, acc1.w);

    if (!LAST) {
        acc0.x = fmaxf(acc0.x, 0.f); acc0.y = fmaxf(acc0.y, 0.f);
        acc0.z = fmaxf(acc0.z, 0.f); acc0.w = fmaxf(acc0.w, 0.f);
        acc1.x = fmaxf(acc1.x, 0.f); acc1.y = fmaxf(acc1.y, 0.f);
        acc1.z = fmaxf(acc1.z, 0.f); acc1.w = fmaxf(acc1.w, 0.f);
        float sum = acc0.x + acc0.y + acc0.z + acc0.w + acc1.x + acc1.y + acc1.z + acc1.w;
        float sq = acc0.x * acc0.x + acc0.y * acc0.y + acc0.z * acc0.z + acc0.w * acc0.w +
                   acc1.x * acc1.x + acc1.y * acc1.y + acc1.z * acc1.z + acc1.w * acc1.w;
        sum = warp_sum(sum);
        sq = warp_sum(sq);
        float mu = sum * (1.f / HH);
        float var = sq * (1.f / HH) - mu * mu;
        float inv = rsqrtf(var + 1e-5f);
        const float4* gp = (const float4*)lng;
        const float4* bp = (const float4*)lnb;
        float4 gg0 = gp[lane], gg1 = gp[lane + 32];
        float4 bb0 = bp[lane], bb1 = bp[lane + 32];
        float4 y0 = make_float4((acc0.x - mu) * inv * gg0.x + bb0.x,
                                (acc0.y - mu) * inv * gg0.y + bb0.y,
                                (acc0.z - mu) * inv * gg0.z + bb0.z,
                                (acc0.w - mu) * inv * gg0.w + bb0.w);
        float4 y1 = make_float4((acc1.x - mu) * inv * gg1.x + bb1.x,
                                (acc1.y - mu) * inv * gg1.y + bb1.y,
                                (acc1.z - mu) * inv * gg1.z + bb1.z,
                                (acc1.w - mu) * inv * gg1.w + bb1.w);
        float4* xw = (float4*)(xout + (size_t)d * HH);
        xw[lane] = y0;
        xw[lane + 32] = y1;
        const float4* wl = (const float4*)attl;
        const float4* wr = (const float4*)attr;
        float sl = dot4(y0, wl[lane]) + dot4(y1, wl[lane + 32]);
        float sr = dot4(y0, wr[lane]) + dot4(y1, wr[lane + 32]);
        sl = warp_sum(sl);
        sr = warp_sum(sr);
        if (lane == 0) { g_al[SLOT_OUT][d] = sl; g_ar[SLOT_OUT][d] = sr; }
    } else {
        float e[CC];
#pragma unroll
        for (int c = 0; c < CC; c++) {
            const float4* wr = (const float4*)(Wl + c * HH);
            float p = dot4(acc0, wr[lane]) + dot4(acc1, wr[lane + 32]);
            e[c] = warp_sum(p);
        }
        if (lane == 0) {
            float val[CC];
            float m = -1e30f;
#pragma unroll
            for (int c = 0; c < CC; c++) {
                val[c] = e[c] + bl[c];
                m = fmaxf(m, val[c]);
            }
            float ssum = 0.f;
#pragma unroll
            for (int c = 0; c < CC; c++) ssum += expf(val[c] - m);
            float lse = m + logf(ssum);
#pragma unroll
            for (int c = 0; c < CC; c++) {
                if (emb_out) emb_out[(size_t)d * CC + c] = val[c];
                logp_out[(size_t)d * CC + c] = val[c] - lse;
            }
        }
    }
}

extern "C" void kernel_launch(void* const* d_in, const int* in_sizes, int n_in,
                              void* d_out, int out_size) {
    const float* x_in = (const float*)d_in[0];
    const int* ei     = (const int*)d_in[1];
    const float* Wi   = (const float*)d_in[2];
    const float* bi   = (const float*)d_in[3];
    const float* attl = (const float*)d_in[4];
    const float* attr = (const float*)d_in[5];
    const float* lng  = (const float*)d_in[6];
    const float* lnb  = (const float*)d_in[7];
    const float* Wl   = (const float*)d_in[8];
    const float* bl   = (const float*)d_in[9];
    float* out = (float*)d_out;

    const int* src = ei;
    const int* dst = ei + EE;

    // CSR build
    k_zero_deg<<<(NN + 255) / 256, 256>>>();
    k_hist<<<(EE + 255) / 256, 256>>>(dst);
    int nb = (NN + 1023) / 1024;
    k_scan_local<<<nb, 1024>>>();
    k_scan_bsum<<<1, 32>>>(nb);
    k_scan_add<<<(NN + 255) / 256, 256>>>();
    k_scatter<<<(EE + 255) / 256, 256>>>(src, dst);

    // init GEMM (f32x2 FFMA2)
    k_transpose<<<(DIN * HH + 255) / 256, 256>>>(Wi);
    dim3 gg((NN + 127) / 128, HH / 128);
    k_gemm<<<gg, 256>>>(x_in, bi);

    int nodeBlocks = (NN + 7) / 8;
    k_prep<<<nodeBlocks, 256>>>(attl, attr);

    float* embp = nullptr;
    float* logp = out;
    if (out_size >= 2 * NN * CC) {
        embp = out;
        logp = out + (size_t)NN * CC;
    }

    k_layer<0, false><<<nodeBlocks, 256>>>(lng + 0 * HH, lnb + 0 * HH,
                                           attl + 1 * HH, attr + 1 * HH,
                                           nullptr, nullptr, nullptr, nullptr);
    k_layer<1, false><<<nodeBlocks, 256>>>(lng + 1 * HH, lnb + 1 * HH,
                                           attl + 2 * HH, attr + 2 * HH,
                                           nullptr, nullptr, nullptr, nullptr);
    k_layer<2, false><<<nodeBlocks, 256>>>(lng + 2 * HH, lnb + 2 * HH,
                                           attl + 3 * HH, attr + 3 * HH,
                                           nullptr, nullptr, nullptr, nullptr);
    k_layer<3, true><<<nodeBlocks, 256>>>(nullptr, nullptr, nullptr, nullptr,
                                          Wl, bl, embp, logp);
}